// round 11
// baseline (speedup 1.0000x reference)
#include <cuda_runtime.h>
#include <cuda_bf16.h>
#include <cstdint>

// Problem dims (fixed)
#define B_   8
#define L_   2048
#define E_   1024
#define M_   (B_ * L_)   // 16384
#define RAD  8

// ---------------------------------------------------------------------------
// Scratch (__device__ globals; allocation-free rule)
// ---------------------------------------------------------------------------
__device__ __nv_bfloat16 g_Xh[(size_t)M_ * E_];
__device__ __nv_bfloat16 g_Xl[(size_t)M_ * E_];
__device__ __nv_bfloat16 g_Wih[(size_t)E_ * E_];
__device__ __nv_bfloat16 g_Wil[(size_t)E_ * E_];
__device__ __nv_bfloat16 g_Woh[(size_t)E_ * E_];
__device__ __nv_bfloat16 g_Wol[(size_t)E_ * E_];
__device__ float         g_Vf [(size_t)M_ * E_];
__device__ __nv_bfloat16 g_Uh[(size_t)M_ * E_];
__device__ __nv_bfloat16 g_Ul[(size_t)M_ * E_];

__device__ __forceinline__ uint32_t smem_u32(const void* p) {
    uint32_t a;
    asm("{ .reg .u64 t; cvta.to.shared.u64 t, %1; cvt.u32.u64 %0, t; }" : "=r"(a) : "l"(p));
    return a;
}

#define CP_ASYNC16(dst, src) \
    asm volatile("cp.async.cg.shared.global [%0], [%1], 16;" :: "r"(dst), "l"(src))
#define CP_COMMIT() asm volatile("cp.async.commit_group;")
#define CP_WAIT(n)  asm volatile("cp.async.wait_group %0;" :: "n"(n))

#define LDSM_X4(r0, r1, r2, r3, addr)                                        \
    asm volatile("ldmatrix.sync.aligned.m8n8.x4.shared.b16 {%0,%1,%2,%3}, [%4];" \
                 : "=r"(r0), "=r"(r1), "=r"(r2), "=r"(r3) : "r"(addr))

#define MMA16816(acc, ar, b0, b1)                                            \
    asm volatile("mma.sync.aligned.m16n8k16.row.col.f32.bf16.bf16.f32 "      \
                 "{%0,%1,%2,%3}, {%4,%5,%6,%7}, {%8,%9}, {%0,%1,%2,%3};"     \
                 : "+f"((acc)[0]), "+f"((acc)[1]), "+f"((acc)[2]), "+f"((acc)[3]) \
                 : "r"((ar)[0]), "r"((ar)[1]), "r"((ar)[2]), "r"((ar)[3]),   \
                   "r"(b0), "r"(b1))

// ---------------------------------------------------------------------------
// GEMM: C[M,1024] = A[M,1024] @ W[1024,1024]^T via bf16 split (3 HMMA terms,
// shared fragments). BM=128, BN=256, BK=32, 256 threads, 8 warps as 2(M)x4(N),
// warp tile 64x64. Per k-step/warp: 16 ldmatrix.x4 vs 96 MMA -> ratio 6
// (R9 had 4; tensor% has tracked this ratio across rounds).
// 3-stage cp.async, stage = Ah8K+Al8K+Wh16K+Wl16K = 48KB, x3 = 144KB, 1 CTA/SM.
// ---------------------------------------------------------------------------
#define GBM 128
#define GBN 256
#define GBK 32
#define NCHUNK (E_ / GBK)   // 32

#define T_AH 0
#define T_AL 8192
#define T_WH 16384
#define T_WL 32768
#define STG_BYTES 49152
#define SM_TOTAL (3 * STG_BYTES)   // 147456

__global__ __launch_bounds__(256, 1) void gemm_mma(
    const __nv_bfloat16* __restrict__ Ah, const __nv_bfloat16* __restrict__ Al,
    const __nv_bfloat16* __restrict__ Wh, const __nv_bfloat16* __restrict__ Wl,
    float* __restrict__ C)
{
    extern __shared__ char smem[];
    const uint32_t smem_base = smem_u32(smem);

    const int tid  = threadIdx.x;
    const int wid  = tid >> 5;
    const int lane = tid & 31;
    const int wm   = wid & 1;    // M offset wm*64
    const int wn   = wid >> 1;   // N offset wn*64

    const size_t mrow0 = (size_t)blockIdx.y * GBM;
    const size_t nrow0 = (size_t)blockIdx.x * GBN;

    // --- cp.async per-thread addressing ---
    // A tiles: 128 rows x 4 segs = 512 x 16B -> 2 reps; W tiles: 256 rows -> 4 reps.
    const int rr = tid >> 2;             // 0..63
    const int sg = tid & 3;
    uint32_t soA[2], soW[4];
    const __nv_bfloat16 *gAh[2], *gAl[2], *gWh[4], *gWl[4];
#pragma unroll
    for (int rep = 0; rep < 2; rep++) {
        const int r = rr + rep * 64;
        soA[rep] = (uint32_t)r * 64 + (uint32_t)((sg * 16) ^ (((r >> 1) & 3) << 4));
        gAh[rep] = Ah + (mrow0 + r) * E_ + sg * 8;
        gAl[rep] = Al + (mrow0 + r) * E_ + sg * 8;
    }
#pragma unroll
    for (int rep = 0; rep < 4; rep++) {
        const int r = rr + rep * 64;
        soW[rep] = (uint32_t)r * 64 + (uint32_t)((sg * 16) ^ (((r >> 1) & 3) << 4));
        gWh[rep] = Wh + (nrow0 + r) * E_ + sg * 8;
        gWl[rep] = Wl + (nrow0 + r) * E_ + sg * 8;
    }

    // --- ldmatrix lane addressing (64B rows) ---
    uint32_t aBase[4], aSwz[4];
#pragma unroll
    for (int mt = 0; mt < 4; mt++) {
        const int r = wm * 64 + mt * 16 + (lane & 15);
        aBase[mt] = (uint32_t)r * 64;
        aSwz[mt]  = (uint32_t)(((r >> 1) & 3) << 4);
    }
    const uint32_t cselA = (uint32_t)(((lane >> 4) & 1) * 16);
    uint32_t bBase[4], bSwz[4];
#pragma unroll
    for (int g = 0; g < 4; g++) {
        const int r = wn * 64 + g * 16 + (lane & 7) + ((lane >> 4) & 1) * 8;
        bBase[g] = (uint32_t)r * 64;
        bSwz[g]  = (uint32_t)(((r >> 1) & 3) << 4);
    }
    const uint32_t cselB = (uint32_t)(((lane >> 3) & 1) * 16);

    float acc[4][8][4];
#pragma unroll
    for (int mt = 0; mt < 4; mt++)
#pragma unroll
        for (int nt = 0; nt < 8; nt++)
#pragma unroll
            for (int r = 0; r < 4; r++) acc[mt][nt][r] = 0.0f;

    auto load_chunk = [&](int ch, int stg) {
        const uint32_t sb = smem_base + (uint32_t)stg * STG_BYTES;
        const int kb = ch * GBK;
#pragma unroll
        for (int rep = 0; rep < 2; rep++) {
            CP_ASYNC16(sb + T_AH + soA[rep], gAh[rep] + kb);
            CP_ASYNC16(sb + T_AL + soA[rep], gAl[rep] + kb);
        }
#pragma unroll
        for (int rep = 0; rep < 4; rep++) {
            CP_ASYNC16(sb + T_WH + soW[rep], gWh[rep] + kb);
            CP_ASYNC16(sb + T_WL + soW[rep], gWl[rep] + kb);
        }
        CP_COMMIT();
    };

    load_chunk(0, 0);
    load_chunk(1, 1);

#pragma unroll 1
    for (int ch = 0; ch < NCHUNK; ch++) {
        if (ch + 1 < NCHUNK) { CP_WAIT(1); } else { CP_WAIT(0); }
        __syncthreads();
        if (ch + 2 < NCHUNK) load_chunk(ch + 2, (ch + 2) % 3);

        const uint32_t sb = smem_base + (uint32_t)(ch % 3) * STG_BYTES;
#pragma unroll
        for (int ks = 0; ks < 2; ks++) {
            const uint32_t kb = (uint32_t)(ks * 32);
            uint32_t ah[4][4], al[4][4];
#pragma unroll
            for (int mt = 0; mt < 4; mt++) {
                const uint32_t off = aBase[mt] + ((kb + cselA) ^ aSwz[mt]);
                LDSM_X4(ah[mt][0], ah[mt][1], ah[mt][2], ah[mt][3], sb + T_AH + off);
                LDSM_X4(al[mt][0], al[mt][1], al[mt][2], al[mt][3], sb + T_AL + off);
            }
#pragma unroll
            for (int g = 0; g < 4; g++) {
                const uint32_t boff = bBase[g] + ((kb + cselB) ^ bSwz[g]);
                uint32_t bh0, bh1, bh2, bh3, bl0, bl1, bl2, bl3;
                LDSM_X4(bh0, bh1, bh2, bh3, sb + T_WH + boff);
                LDSM_X4(bl0, bl1, bl2, bl3, sb + T_WL + boff);
#pragma unroll
                for (int mt = 0; mt < 4; mt++) {
                    MMA16816(acc[mt][g * 2],     ah[mt], bh0, bh1);
                    MMA16816(acc[mt][g * 2 + 1], ah[mt], bh2, bh3);
                    MMA16816(acc[mt][g * 2],     ah[mt], bl0, bl1);
                    MMA16816(acc[mt][g * 2 + 1], ah[mt], bl2, bl3);
                    MMA16816(acc[mt][g * 2],     al[mt], bh0, bh1);
                    MMA16816(acc[mt][g * 2 + 1], al[mt], bh2, bh3);
                }
            }
        }
    }

    // Epilogue: warp tile rows wm*64+mt*16+{qr,qr+8}, cols wn*64+nt*8+qc.
    const int qr = lane >> 2;
    const int qc = (lane & 3) * 2;
#pragma unroll
    for (int mt = 0; mt < 4; mt++) {
        const size_t r0e = mrow0 + wm * 64 + mt * 16 + qr;
#pragma unroll
        for (int nt = 0; nt < 8; nt++) {
            const size_t col = nrow0 + wn * 64 + nt * 8 + qc;
            *(float2*)(C + r0e * E_ + col)       = make_float2(acc[mt][nt][0], acc[mt][nt][1]);
            *(float2*)(C + (r0e + 8) * E_ + col) = make_float2(acc[mt][nt][2], acc[mt][nt][3]);
        }
    }
}

// ---------------------------------------------------------------------------
// fp32 -> bf16 hi/lo split conversion (float4 vectorized)
// ---------------------------------------------------------------------------
__global__ __launch_bounds__(256) void conv_split(
    const float* __restrict__ in, __nv_bfloat16* __restrict__ hi,
    __nv_bfloat16* __restrict__ lo, int n4)
{
    int idx = blockIdx.x * 256 + threadIdx.x;
    if (idx >= n4) return;
    float4 v = ((const float4*)in)[idx];
    __nv_bfloat16 h0 = __float2bfloat16(v.x), h1 = __float2bfloat16(v.y);
    __nv_bfloat16 h2 = __float2bfloat16(v.z), h3 = __float2bfloat16(v.w);
    __nv_bfloat16 l0 = __float2bfloat16(v.x - __bfloat162float(h0));
    __nv_bfloat16 l1 = __float2bfloat16(v.y - __bfloat162float(h1));
    __nv_bfloat16 l2 = __float2bfloat16(v.z - __bfloat162float(h2));
    __nv_bfloat16 l3 = __float2bfloat16(v.w - __bfloat162float(h3));
    __nv_bfloat162 hp0; hp0.x = h0; hp0.y = h1;
    __nv_bfloat162 hp1; hp1.x = h2; hp1.y = h3;
    __nv_bfloat162 lp0; lp0.x = l0; lp0.y = l1;
    __nv_bfloat162 lp1; lp1.x = l2; lp1.y = l3;
    uint2 hw, lw;
    hw.x = *(uint32_t*)&hp0; hw.y = *(uint32_t*)&hp1;
    lw.x = *(uint32_t*)&lp0; lw.y = *(uint32_t*)&lp1;
    ((uint2*)hi)[idx] = hw;
    ((uint2*)lo)[idx] = lw;
}

// ---------------------------------------------------------------------------
// Gaussian smoothing along sequence (17 taps, float4 over embed dim),
// reading fp32 V, writing bf16 hi/lo U for GEMM2.
// ---------------------------------------------------------------------------
__global__ __launch_bounds__(256) void smooth_kernel(
    const float* __restrict__ V, __nv_bfloat16* __restrict__ Uh,
    __nv_bfloat16* __restrict__ Ul)
{
    const float wt[RAD + 1] = {1.0f, 0.60653066f, 0.13533528f, 0.011108997f,
                               3.3546263e-4f, 3.7266532e-6f, 1.5229979e-8f,
                               2.2897348e-11f, 1.2664166e-14f};
    const int n = blockIdx.x;        // b*L + q
    const int b = n >> 11;
    const int q = n & (L_ - 1);
    const int e = threadIdx.x * 4;   // 4 consecutive embed cols
    const int h = e >> 7;            // head

    int c;
    switch (h) {
        case 0: case 5: c = q;      break;   // center
        case 1: case 6: c = q - 1;  break;   // left
        case 2: case 7: c = q + 1;  break;   // right
        case 3:         c = 0;      break;   // first
        default:        c = L_ - 1; break;   // last
    }

    float ax = 0.f, ay = 0.f, az = 0.f, aw = 0.f, wsum = 0.f;
#pragma unroll
    for (int d = -RAD; d <= RAD; d++) {
        const int j = c + d;
        if (j >= 0 && j < L_) {
            const float w = wt[d < 0 ? -d : d];
            wsum += w;
            const float4 v = *(const float4*)(V + ((size_t)b * L_ + j) * E_ + e);
            ax = fmaf(w, v.x, ax); ay = fmaf(w, v.y, ay);
            az = fmaf(w, v.z, az); aw = fmaf(w, v.w, aw);
        }
    }
    const float inv = 1.0f / wsum;
    ax *= inv; ay *= inv; az *= inv; aw *= inv;

    __nv_bfloat16 h0 = __float2bfloat16(ax), h1 = __float2bfloat16(ay);
    __nv_bfloat16 h2 = __float2bfloat16(az), h3 = __float2bfloat16(aw);
    __nv_bfloat16 l0 = __float2bfloat16(ax - __bfloat162float(h0));
    __nv_bfloat16 l1 = __float2bfloat16(ay - __bfloat162float(h1));
    __nv_bfloat16 l2 = __float2bfloat16(az - __bfloat162float(h2));
    __nv_bfloat16 l3 = __float2bfloat16(aw - __bfloat162float(h3));
    __nv_bfloat162 hp0; hp0.x = h0; hp0.y = h1;
    __nv_bfloat162 hp1; hp1.x = h2; hp1.y = h3;
    __nv_bfloat162 lp0; lp0.x = l0; lp0.y = l1;
    __nv_bfloat162 lp1; lp1.x = l2; lp1.y = l3;
    uint2 hw, lw;
    hw.x = *(uint32_t*)&hp0; hw.y = *(uint32_t*)&hp1;
    lw.x = *(uint32_t*)&lp0; lw.y = *(uint32_t*)&lp1;
    const size_t o = ((size_t)n * E_ + e) >> 2;
    ((uint2*)Uh)[o] = hw;
    ((uint2*)Ul)[o] = lw;
}

// ---------------------------------------------------------------------------
extern "C" void kernel_launch(void* const* d_in, const int* in_sizes, int n_in,
                              void* d_out, int out_size)
{
    (void)in_sizes; (void)n_in; (void)out_size;
    const float* x     = (const float*)d_in[0];
    const float* W_in  = (const float*)d_in[1];
    const float* W_out = (const float*)d_in[2];
    float* out = (float*)d_out;

    __nv_bfloat16 *Xh, *Xl, *Wih, *Wil, *Woh, *Wol, *Uh, *Ul;
    float* Vf;
    cudaGetSymbolAddress((void**)&Xh, g_Xh);
    cudaGetSymbolAddress((void**)&Xl, g_Xl);
    cudaGetSymbolAddress((void**)&Wih, g_Wih);
    cudaGetSymbolAddress((void**)&Wil, g_Wil);
    cudaGetSymbolAddress((void**)&Woh, g_Woh);
    cudaGetSymbolAddress((void**)&Wol, g_Wol);
    cudaGetSymbolAddress((void**)&Vf, g_Vf);
    cudaGetSymbolAddress((void**)&Uh, g_Uh);
    cudaGetSymbolAddress((void**)&Ul, g_Ul);

    cudaFuncSetAttribute(gemm_mma, cudaFuncAttributeMaxDynamicSharedMemorySize, SM_TOTAL);

    // Split conversions
    conv_split<<<(M_ * E_ / 4 + 255) / 256, 256>>>(x, Xh, Xl, M_ * E_ / 4);
    conv_split<<<(E_ * E_ / 4 + 255) / 256, 256>>>(W_in, Wih, Wil, E_ * E_ / 4);
    conv_split<<<(E_ * E_ / 4 + 255) / 256, 256>>>(W_out, Woh, Wol, E_ * E_ / 4);

    dim3 gridGemm(E_ / GBN, M_ / GBM);   // (4, 128) = 512 CTAs
    // V = X @ W_in^T   (fp32 out for smoothing)
    gemm_mma<<<gridGemm, 256, SM_TOTAL>>>(Xh, Xl, Wih, Wil, Vf);
    // U = gaussian smooth of V (bf16 hi/lo out)
    smooth_kernel<<<M_, 256>>>(Vf, Uh, Ul);
    // out = U @ W_out^T (fp32 out)
    gemm_mma<<<gridGemm, 256, SM_TOTAL>>>(Uh, Ul, Woh, Wol, out);
}

// round 12
// speedup vs baseline: 1.2189x; 1.2189x over previous
#include <cuda_runtime.h>
#include <cuda_bf16.h>
#include <cstdint>

// Problem dims (fixed)
#define B_   8
#define L_   2048
#define E_   1024
#define M_   (B_ * L_)   // 16384
#define RAD  8
#define KP_  768         // packed K for GEMM2 (heads 3,4 removed)

// ---------------------------------------------------------------------------
// Scratch (__device__ globals; allocation-free rule)
// ---------------------------------------------------------------------------
__device__ __nv_bfloat16 g_Xh[(size_t)M_ * E_];
__device__ __nv_bfloat16 g_Xl[(size_t)M_ * E_];
__device__ __nv_bfloat16 g_Wih[(size_t)E_ * E_];
__device__ __nv_bfloat16 g_Wil[(size_t)E_ * E_];
__device__ __nv_bfloat16 g_Wph[(size_t)E_ * KP_];   // W_out packed (K=768)
__device__ __nv_bfloat16 g_Wpl[(size_t)E_ * KP_];
__device__ float         g_Vf [(size_t)M_ * E_];
__device__ __nv_bfloat16 g_Uh[(size_t)M_ * KP_];    // packed U (6 heads)
__device__ __nv_bfloat16 g_Ul[(size_t)M_ * KP_];
__device__ float         g_ubar[B_ * 256];          // per-batch const-head values
__device__ float         g_yv[B_ * E_];             // per-batch broadcast output

__device__ __forceinline__ uint32_t smem_u32(const void* p) {
    uint32_t a;
    asm("{ .reg .u64 t; cvta.to.shared.u64 t, %1; cvt.u32.u64 %0, t; }" : "=r"(a) : "l"(p));
    return a;
}

#define CP_ASYNC16(dst, src) \
    asm volatile("cp.async.cg.shared.global [%0], [%1], 16;" :: "r"(dst), "l"(src))
#define CP_COMMIT() asm volatile("cp.async.commit_group;")
#define CP_WAIT(n)  asm volatile("cp.async.wait_group %0;" :: "n"(n))

#define LDSM_X4(r0, r1, r2, r3, addr)                                        \
    asm volatile("ldmatrix.sync.aligned.m8n8.x4.shared.b16 {%0,%1,%2,%3}, [%4];" \
                 : "=r"(r0), "=r"(r1), "=r"(r2), "=r"(r3) : "r"(addr))

#define MMA16816(acc, ar, b0, b1)                                            \
    asm volatile("mma.sync.aligned.m16n8k16.row.col.f32.bf16.bf16.f32 "      \
                 "{%0,%1,%2,%3}, {%4,%5,%6,%7}, {%8,%9}, {%0,%1,%2,%3};"     \
                 : "+f"((acc)[0]), "+f"((acc)[1]), "+f"((acc)[2]), "+f"((acc)[3]) \
                 : "r"((ar)[0]), "r"((ar)[1]), "r"((ar)[2]), "r"((ar)[3]),   \
                   "r"(b0), "r"(b1))

// ---------------------------------------------------------------------------
// GEMM (R9 config, templated K/stride): C[M,1024] = A[M,KD] @ W[1024,KD]^T
// via bf16 split (3 HMMA terms, shared fragments). BM=BN=128, BK=32,
// 256 threads, warp tile 32x64, 3-stage cp.async, 2 CTAs/SM.
// ADDY: epilogue adds per-batch broadcast vector yv[b*1024+col].
// ---------------------------------------------------------------------------
#define GBM 128
#define GBN 128
#define GBK 32

#define T_AH 0
#define T_AL 8192
#define T_WH 16384
#define T_WL 24576
#define STG_BYTES 32768
#define SM_TOTAL (3 * STG_BYTES)   // 98304

template <int KD, bool ADDY>
__global__ __launch_bounds__(256, 2) void gemm_mma(
    const __nv_bfloat16* __restrict__ Ah, const __nv_bfloat16* __restrict__ Al,
    const __nv_bfloat16* __restrict__ Wh, const __nv_bfloat16* __restrict__ Wl,
    float* __restrict__ C, const float* __restrict__ yv)
{
    constexpr int NCHUNK = KD / GBK;
    extern __shared__ char smem[];
    const uint32_t smem_base = smem_u32(smem);

    const int tid  = threadIdx.x;
    const int wid  = tid >> 5;
    const int lane = tid & 31;
    const int wm   = wid & 3;    // M offset wm*32
    const int wn   = wid >> 2;   // N offset wn*64

    const size_t mrow0 = (size_t)blockIdx.y * GBM;
    const size_t nrow0 = (size_t)blockIdx.x * GBN;

    // --- cp.async per-thread addressing (tile: 128 rows x 4 x 16B) ---
    const int r0 = tid >> 2;
    const int r1 = r0 + 64;
    const int sg = tid & 3;
    const uint32_t so0 = (uint32_t)r0 * 64 + (uint32_t)((sg * 16) ^ (((r0 >> 1) & 3) << 4));
    const uint32_t so1 = (uint32_t)r1 * 64 + (uint32_t)((sg * 16) ^ (((r1 >> 1) & 3) << 4));
    const __nv_bfloat16* gAh0 = Ah + (mrow0 + r0) * KD + sg * 8;
    const __nv_bfloat16* gAh1 = Ah + (mrow0 + r1) * KD + sg * 8;
    const __nv_bfloat16* gAl0 = Al + (mrow0 + r0) * KD + sg * 8;
    const __nv_bfloat16* gAl1 = Al + (mrow0 + r1) * KD + sg * 8;
    const __nv_bfloat16* gWh0 = Wh + (nrow0 + r0) * KD + sg * 8;
    const __nv_bfloat16* gWh1 = Wh + (nrow0 + r1) * KD + sg * 8;
    const __nv_bfloat16* gWl0 = Wl + (nrow0 + r0) * KD + sg * 8;
    const __nv_bfloat16* gWl1 = Wl + (nrow0 + r1) * KD + sg * 8;

    // --- ldmatrix lane addressing (64B rows) ---
    uint32_t aBase[2], aSwz[2];
#pragma unroll
    for (int mt = 0; mt < 2; mt++) {
        const int r = wm * 32 + mt * 16 + (lane & 15);
        aBase[mt] = (uint32_t)r * 64;
        aSwz[mt]  = (uint32_t)(((r >> 1) & 3) << 4);
    }
    const uint32_t cselA = (uint32_t)(((lane >> 4) & 1) * 16);
    uint32_t bBase[4], bSwz[4];
#pragma unroll
    for (int g = 0; g < 4; g++) {
        const int r = wn * 64 + g * 16 + (lane & 7) + ((lane >> 4) & 1) * 8;
        bBase[g] = (uint32_t)r * 64;
        bSwz[g]  = (uint32_t)(((r >> 1) & 3) << 4);
    }
    const uint32_t cselB = (uint32_t)(((lane >> 3) & 1) * 16);

    float acc[2][8][4];
#pragma unroll
    for (int mt = 0; mt < 2; mt++)
#pragma unroll
        for (int nt = 0; nt < 8; nt++)
#pragma unroll
            for (int r = 0; r < 4; r++) acc[mt][nt][r] = 0.0f;

    auto load_chunk = [&](int ch, int stg) {
        const uint32_t sb = smem_base + (uint32_t)stg * STG_BYTES;
        const int kb = ch * GBK;
        CP_ASYNC16(sb + T_AH + so0, gAh0 + kb);
        CP_ASYNC16(sb + T_AH + so1, gAh1 + kb);
        CP_ASYNC16(sb + T_AL + so0, gAl0 + kb);
        CP_ASYNC16(sb + T_AL + so1, gAl1 + kb);
        CP_ASYNC16(sb + T_WH + so0, gWh0 + kb);
        CP_ASYNC16(sb + T_WH + so1, gWh1 + kb);
        CP_ASYNC16(sb + T_WL + so0, gWl0 + kb);
        CP_ASYNC16(sb + T_WL + so1, gWl1 + kb);
        CP_COMMIT();
    };

    load_chunk(0, 0);
    load_chunk(1, 1);

#pragma unroll 1
    for (int ch = 0; ch < NCHUNK; ch++) {
        if (ch + 1 < NCHUNK) { CP_WAIT(1); } else { CP_WAIT(0); }
        __syncthreads();
        if (ch + 2 < NCHUNK) load_chunk(ch + 2, (ch + 2) % 3);

        const uint32_t sb = smem_base + (uint32_t)(ch % 3) * STG_BYTES;
#pragma unroll
        for (int ks = 0; ks < 2; ks++) {
            const uint32_t kb = (uint32_t)(ks * 32);
            uint32_t ah[2][4], al[2][4];
#pragma unroll
            for (int mt = 0; mt < 2; mt++) {
                const uint32_t off = aBase[mt] + ((kb + cselA) ^ aSwz[mt]);
                LDSM_X4(ah[mt][0], ah[mt][1], ah[mt][2], ah[mt][3], sb + T_AH + off);
                LDSM_X4(al[mt][0], al[mt][1], al[mt][2], al[mt][3], sb + T_AL + off);
            }
#pragma unroll
            for (int g = 0; g < 4; g++) {
                const uint32_t boff = bBase[g] + ((kb + cselB) ^ bSwz[g]);
                uint32_t bh0, bh1, bh2, bh3, bl0, bl1, bl2, bl3;
                LDSM_X4(bh0, bh1, bh2, bh3, sb + T_WH + boff);
                LDSM_X4(bl0, bl1, bl2, bl3, sb + T_WL + boff);
#pragma unroll
                for (int mt = 0; mt < 2; mt++) {
                    MMA16816(acc[mt][g * 2],     ah[mt], bh0, bh1);
                    MMA16816(acc[mt][g * 2 + 1], ah[mt], bh2, bh3);
                    MMA16816(acc[mt][g * 2],     ah[mt], bl0, bl1);
                    MMA16816(acc[mt][g * 2 + 1], ah[mt], bl2, bl3);
                    MMA16816(acc[mt][g * 2],     al[mt], bh0, bh1);
                    MMA16816(acc[mt][g * 2 + 1], al[mt], bh2, bh3);
                }
            }
        }
    }

    // Epilogue (C stride is always E_=1024)
    const int qr = lane >> 2;
    const int qc = (lane & 3) * 2;
#pragma unroll
    for (int mt = 0; mt < 2; mt++) {
        const size_t r0e = mrow0 + wm * 32 + mt * 16 + qr;
        const int bb = (int)(r0e >> 11);
#pragma unroll
        for (int nt = 0; nt < 8; nt++) {
            const size_t col = nrow0 + wn * 64 + nt * 8 + qc;
            float a0 = acc[mt][nt][0], a1 = acc[mt][nt][1];
            float a2 = acc[mt][nt][2], a3 = acc[mt][nt][3];
            if (ADDY) {
                const float y0 = __ldg(yv + (size_t)bb * E_ + col);
                const float y1 = __ldg(yv + (size_t)bb * E_ + col + 1);
                a0 += y0; a1 += y1; a2 += y0; a3 += y1;
            }
            *(float2*)(C + r0e * E_ + col)       = make_float2(a0, a1);
            *(float2*)(C + (r0e + 8) * E_ + col) = make_float2(a2, a3);
        }
    }
}

// ---------------------------------------------------------------------------
// fp32 -> bf16 hi/lo split conversion (full width)
// ---------------------------------------------------------------------------
__global__ __launch_bounds__(256) void conv_split(
    const float* __restrict__ in, __nv_bfloat16* __restrict__ hi,
    __nv_bfloat16* __restrict__ lo, int n4)
{
    int idx = blockIdx.x * 256 + threadIdx.x;
    if (idx >= n4) return;
    float4 v = ((const float4*)in)[idx];
    __nv_bfloat16 h0 = __float2bfloat16(v.x), h1 = __float2bfloat16(v.y);
    __nv_bfloat16 h2 = __float2bfloat16(v.z), h3 = __float2bfloat16(v.w);
    __nv_bfloat16 l0 = __float2bfloat16(v.x - __bfloat162float(h0));
    __nv_bfloat16 l1 = __float2bfloat16(v.y - __bfloat162float(h1));
    __nv_bfloat16 l2 = __float2bfloat16(v.z - __bfloat162float(h2));
    __nv_bfloat16 l3 = __float2bfloat16(v.w - __bfloat162float(h3));
    __nv_bfloat162 hp0; hp0.x = h0; hp0.y = h1;
    __nv_bfloat162 hp1; hp1.x = h2; hp1.y = h3;
    __nv_bfloat162 lp0; lp0.x = l0; lp0.y = l1;
    __nv_bfloat162 lp1; lp1.x = l2; lp1.y = l3;
    uint2 hw, lw;
    hw.x = *(uint32_t*)&hp0; hw.y = *(uint32_t*)&hp1;
    lw.x = *(uint32_t*)&lp0; lw.y = *(uint32_t*)&lp1;
    ((uint2*)hi)[idx] = hw;
    ((uint2*)lo)[idx] = lw;
}

// ---------------------------------------------------------------------------
// W_out packed split: rows 1024, K cols {0:384, 640:1024} -> [1024, 768]
// ---------------------------------------------------------------------------
__global__ __launch_bounds__(256) void conv_split_pack(
    const float* __restrict__ in, __nv_bfloat16* __restrict__ hi,
    __nv_bfloat16* __restrict__ lo)
{
    int idx = blockIdx.x * 256 + threadIdx.x;   // over E_*KP_/4
    if (idx >= E_ * KP_ / 4) return;
    const int pos = idx * 4;
    const int n   = pos / KP_;
    const int kp  = pos % KP_;
    const int k   = kp < 384 ? kp : kp + 256;
    float4 v = *(const float4*)(in + (size_t)n * E_ + k);
    __nv_bfloat16 h0 = __float2bfloat16(v.x), h1 = __float2bfloat16(v.y);
    __nv_bfloat16 h2 = __float2bfloat16(v.z), h3 = __float2bfloat16(v.w);
    __nv_bfloat16 l0 = __float2bfloat16(v.x - __bfloat162float(h0));
    __nv_bfloat16 l1 = __float2bfloat16(v.y - __bfloat162float(h1));
    __nv_bfloat16 l2 = __float2bfloat16(v.z - __bfloat162float(h2));
    __nv_bfloat16 l3 = __float2bfloat16(v.w - __bfloat162float(h3));
    __nv_bfloat162 hp0; hp0.x = h0; hp0.y = h1;
    __nv_bfloat162 hp1; hp1.x = h2; hp1.y = h3;
    __nv_bfloat162 lp0; lp0.x = l0; lp0.y = l1;
    __nv_bfloat162 lp1; lp1.x = l2; lp1.y = l3;
    uint2 hw, lw;
    hw.x = *(uint32_t*)&hp0; hw.y = *(uint32_t*)&hp1;
    lw.x = *(uint32_t*)&lp0; lw.y = *(uint32_t*)&lp1;
    ((uint2*)hi)[idx] = hw;
    ((uint2*)lo)[idx] = lw;
}

__device__ __constant__ float c_wt[RAD + 1] = {
    1.0f, 0.60653066f, 0.13533528f, 0.011108997f, 3.3546263e-4f,
    3.7266532e-6f, 1.5229979e-8f, 2.2897348e-11f, 1.2664166e-14f};

// ---------------------------------------------------------------------------
// Gaussian smoothing, 6 non-constant heads only, packed output [M, 768].
// ---------------------------------------------------------------------------
__global__ __launch_bounds__(192) void smooth_pack(
    const float* __restrict__ V, __nv_bfloat16* __restrict__ Uh,
    __nv_bfloat16* __restrict__ Ul)
{
    const int n = blockIdx.x;        // b*L + q
    const int b = n >> 11;
    const int q = n & (L_ - 1);
    const int kp = threadIdx.x * 4;  // packed col
    const int hp = kp >> 7;          // 0..5
    const int vcol = kp < 384 ? kp : kp + 256;

    int c;
    switch (hp % 3) {
        case 0:  c = q;     break;   // center
        case 1:  c = q - 1; break;   // left
        default: c = q + 1; break;   // right
    }

    float ax = 0.f, ay = 0.f, az = 0.f, aw = 0.f, wsum = 0.f;
#pragma unroll
    for (int d = -RAD; d <= RAD; d++) {
        const int j = c + d;
        if (j >= 0 && j < L_) {
            const float w = c_wt[d < 0 ? -d : d];
            wsum += w;
            const float4 v = *(const float4*)(V + ((size_t)b * L_ + j) * E_ + vcol);
            ax = fmaf(w, v.x, ax); ay = fmaf(w, v.y, ay);
            az = fmaf(w, v.z, az); aw = fmaf(w, v.w, aw);
        }
    }
    const float inv = 1.0f / wsum;
    ax *= inv; ay *= inv; az *= inv; aw *= inv;

    __nv_bfloat16 h0 = __float2bfloat16(ax), h1 = __float2bfloat16(ay);
    __nv_bfloat16 h2 = __float2bfloat16(az), h3 = __float2bfloat16(aw);
    __nv_bfloat16 l0 = __float2bfloat16(ax - __bfloat162float(h0));
    __nv_bfloat16 l1 = __float2bfloat16(ay - __bfloat162float(h1));
    __nv_bfloat16 l2 = __float2bfloat16(az - __bfloat162float(h2));
    __nv_bfloat16 l3 = __float2bfloat16(aw - __bfloat162float(h3));
    __nv_bfloat162 hp0; hp0.x = h0; hp0.y = h1;
    __nv_bfloat162 hp1; hp1.x = h2; hp1.y = h3;
    __nv_bfloat162 lp0; lp0.x = l0; lp0.y = l1;
    __nv_bfloat162 lp1; lp1.x = l2; lp1.y = l3;
    uint2 hw, lw;
    hw.x = *(uint32_t*)&hp0; hw.y = *(uint32_t*)&hp1;
    lw.x = *(uint32_t*)&lp0; lw.y = *(uint32_t*)&lp1;
    const size_t o = ((size_t)n * KP_ + kp) >> 2;
    ((uint2*)Uh)[o] = hw;
    ((uint2*)Ul)[o] = lw;
}

// ---------------------------------------------------------------------------
// Per-batch constant-head values: ubar[b][p], p in 0..255 (V col 384+p).
// p<128: head 'first' (center 0, taps j=0..8). p>=128: head 'last'
// (center L-1, taps j=L-9..L-1).
// ---------------------------------------------------------------------------
__global__ void ubar_kernel(const float* __restrict__ V, float* __restrict__ ubar)
{
    const int b = blockIdx.x;
    const int p = threadIdx.x;      // 0..255
    const int c = 384 + p;
    float acc = 0.f, wsum = 0.f;
    if (p < 128) {
#pragma unroll
        for (int j = 0; j <= RAD; j++) {
            const float w = c_wt[j];
            wsum += w;
            acc = fmaf(w, V[((size_t)b * L_ + j) * E_ + c], acc);
        }
    } else {
#pragma unroll
        for (int d = 0; d <= RAD; d++) {
            const float w = c_wt[d];
            wsum += w;
            acc = fmaf(w, V[((size_t)b * L_ + (L_ - 1 - d)) * E_ + c], acc);
        }
    }
    ubar[b * 256 + p] = acc / wsum;
}

// ---------------------------------------------------------------------------
// y[b][n] = sum_p ubar[b][p] * W_out[n][384+p]   (fp32, exact)
// ---------------------------------------------------------------------------
__global__ __launch_bounds__(256) void yvec_kernel(
    const float* __restrict__ ubar, const float* __restrict__ Wout,
    float* __restrict__ yv)
{
    __shared__ float us[256];
    const int b = blockIdx.x >> 2;
    const int n = (blockIdx.x & 3) * 256 + threadIdx.x;
    us[threadIdx.x] = ubar[b * 256 + threadIdx.x];
    __syncthreads();
    float acc = 0.f;
    const float* wr = Wout + (size_t)n * E_ + 384;
#pragma unroll 8
    for (int p = 0; p < 256; p++) acc = fmaf(us[p], wr[p], acc);
    yv[b * E_ + n] = acc;
}

// ---------------------------------------------------------------------------
extern "C" void kernel_launch(void* const* d_in, const int* in_sizes, int n_in,
                              void* d_out, int out_size)
{
    (void)in_sizes; (void)n_in; (void)out_size;
    const float* x     = (const float*)d_in[0];
    const float* W_in  = (const float*)d_in[1];
    const float* W_out = (const float*)d_in[2];
    float* out = (float*)d_out;

    __nv_bfloat16 *Xh, *Xl, *Wih, *Wil, *Wph, *Wpl, *Uh, *Ul;
    float *Vf, *ubar, *yv;
    cudaGetSymbolAddress((void**)&Xh, g_Xh);
    cudaGetSymbolAddress((void**)&Xl, g_Xl);
    cudaGetSymbolAddress((void**)&Wih, g_Wih);
    cudaGetSymbolAddress((void**)&Wil, g_Wil);
    cudaGetSymbolAddress((void**)&Wph, g_Wph);
    cudaGetSymbolAddress((void**)&Wpl, g_Wpl);
    cudaGetSymbolAddress((void**)&Vf, g_Vf);
    cudaGetSymbolAddress((void**)&Uh, g_Uh);
    cudaGetSymbolAddress((void**)&Ul, g_Ul);
    cudaGetSymbolAddress((void**)&ubar, g_ubar);
    cudaGetSymbolAddress((void**)&yv, g_yv);

    cudaFuncSetAttribute(gemm_mma<E_, false>, cudaFuncAttributeMaxDynamicSharedMemorySize, SM_TOTAL);
    cudaFuncSetAttribute(gemm_mma<KP_, true>, cudaFuncAttributeMaxDynamicSharedMemorySize, SM_TOTAL);

    // Split conversions
    conv_split<<<(M_ * E_ / 4 + 255) / 256, 256>>>(x, Xh, Xl, M_ * E_ / 4);
    conv_split<<<(E_ * E_ / 4 + 255) / 256, 256>>>(W_in, Wih, Wil, E_ * E_ / 4);
    conv_split_pack<<<(E_ * KP_ / 4 + 255) / 256, 256>>>(W_out, Wph, Wpl);

    dim3 gridGemm(E_ / GBN, M_ / GBM);   // (8, 128)
    // V = X @ W_in^T  (fp32, full K)
    gemm_mma<E_, false><<<gridGemm, 256, SM_TOTAL>>>(Xh, Xl, Wih, Wil, Vf, nullptr);
    // per-batch constant-head path
    ubar_kernel<<<B_, 256>>>(Vf, ubar);
    yvec_kernel<<<B_ * 4, 256>>>(ubar, W_out, yv);
    // U (packed, 6 heads) = gaussian smooth of V
    smooth_pack<<<M_, 192>>>(Vf, Uh, Ul);
    // out = U_packed @ W_out_packed^T + broadcast(yv)
    gemm_mma<KP_, true><<<gridGemm, 256, SM_TOTAL>>>(Uh, Ul, Wph, Wpl, out, yv);
}

// round 13
// speedup vs baseline: 1.2395x; 1.0169x over previous
#include <cuda_runtime.h>
#include <cuda_bf16.h>
#include <cstdint>

// Problem dims (fixed)
#define B_   8
#define L_   2048
#define E_   1024
#define M_   (B_ * L_)   // 16384
#define RAD  5           // Gaussian truncation; dropped mass ~3e-6 rel (renormalized)
#define KP_  768         // packed K for GEMM2 (heads 3,4 removed)

// ---------------------------------------------------------------------------
// Scratch (__device__ globals; allocation-free rule)
// ---------------------------------------------------------------------------
__device__ __nv_bfloat16 g_Xh[(size_t)M_ * E_];
__device__ __nv_bfloat16 g_Xl[(size_t)M_ * E_];
__device__ __nv_bfloat16 g_Wih[(size_t)E_ * E_];
__device__ __nv_bfloat16 g_Wil[(size_t)E_ * E_];
__device__ __nv_bfloat16 g_Wph[(size_t)E_ * KP_];   // W_out packed (K=768)
__device__ __nv_bfloat16 g_Wpl[(size_t)E_ * KP_];
__device__ float         g_Vf [(size_t)M_ * E_];
__device__ __nv_bfloat16 g_Uh[(size_t)M_ * KP_];    // packed U (6 heads)
__device__ __nv_bfloat16 g_Ul[(size_t)M_ * KP_];
__device__ float         g_ubar[B_ * 256];          // per-batch const-head values
__device__ float         g_yv[B_ * E_];             // per-batch broadcast output

__device__ __forceinline__ uint32_t smem_u32(const void* p) {
    uint32_t a;
    asm("{ .reg .u64 t; cvta.to.shared.u64 t, %1; cvt.u32.u64 %0, t; }" : "=r"(a) : "l"(p));
    return a;
}

#define CP_ASYNC16(dst, src) \
    asm volatile("cp.async.cg.shared.global [%0], [%1], 16;" :: "r"(dst), "l"(src))
#define CP_COMMIT() asm volatile("cp.async.commit_group;")
#define CP_WAIT(n)  asm volatile("cp.async.wait_group %0;" :: "n"(n))

#define LDSM_X4(r0, r1, r2, r3, addr)                                        \
    asm volatile("ldmatrix.sync.aligned.m8n8.x4.shared.b16 {%0,%1,%2,%3}, [%4];" \
                 : "=r"(r0), "=r"(r1), "=r"(r2), "=r"(r3) : "r"(addr))

#define MMA16816(acc, ar, b0, b1)                                            \
    asm volatile("mma.sync.aligned.m16n8k16.row.col.f32.bf16.bf16.f32 "      \
                 "{%0,%1,%2,%3}, {%4,%5,%6,%7}, {%8,%9}, {%0,%1,%2,%3};"     \
                 : "+f"((acc)[0]), "+f"((acc)[1]), "+f"((acc)[2]), "+f"((acc)[3]) \
                 : "r"((ar)[0]), "r"((ar)[1]), "r"((ar)[2]), "r"((ar)[3]),   \
                   "r"(b0), "r"(b1))

// ---------------------------------------------------------------------------
// GEMM (templated K/stride): C[M,1024] = A[M,KD] @ W[1024,KD]^T via bf16
// split (3 HMMA terms, shared fragments). BM=BN=128, BK=32, 256 threads,
// warp tile 32x64, 3-stage cp.async, 2 CTAs/SM.
// MMA order: two B-groups paired, term-blocks of 8 distinct accumulators
// -> RAW reuse distance 8 MMAs (was 2).
// ADDY: epilogue adds per-batch broadcast vector yv[b*1024+col].
// ---------------------------------------------------------------------------
#define GBM 128
#define GBN 128
#define GBK 32

#define T_AH 0
#define T_AL 8192
#define T_WH 16384
#define T_WL 24576
#define STG_BYTES 32768
#define SM_TOTAL (3 * STG_BYTES)   // 98304

template <int KD, bool ADDY>
__global__ __launch_bounds__(256, 2) void gemm_mma(
    const __nv_bfloat16* __restrict__ Ah, const __nv_bfloat16* __restrict__ Al,
    const __nv_bfloat16* __restrict__ Wh, const __nv_bfloat16* __restrict__ Wl,
    float* __restrict__ C, const float* __restrict__ yv)
{
    constexpr int NCHUNK = KD / GBK;
    extern __shared__ char smem[];
    const uint32_t smem_base = smem_u32(smem);

    const int tid  = threadIdx.x;
    const int wid  = tid >> 5;
    const int lane = tid & 31;
    const int wm   = wid & 3;    // M offset wm*32
    const int wn   = wid >> 2;   // N offset wn*64

    const size_t mrow0 = (size_t)blockIdx.y * GBM;
    const size_t nrow0 = (size_t)blockIdx.x * GBN;

    // --- cp.async per-thread addressing (tile: 128 rows x 4 x 16B) ---
    const int r0 = tid >> 2;
    const int r1 = r0 + 64;
    const int sg = tid & 3;
    const uint32_t so0 = (uint32_t)r0 * 64 + (uint32_t)((sg * 16) ^ (((r0 >> 1) & 3) << 4));
    const uint32_t so1 = (uint32_t)r1 * 64 + (uint32_t)((sg * 16) ^ (((r1 >> 1) & 3) << 4));
    const __nv_bfloat16* gAh0 = Ah + (mrow0 + r0) * KD + sg * 8;
    const __nv_bfloat16* gAh1 = Ah + (mrow0 + r1) * KD + sg * 8;
    const __nv_bfloat16* gAl0 = Al + (mrow0 + r0) * KD + sg * 8;
    const __nv_bfloat16* gAl1 = Al + (mrow0 + r1) * KD + sg * 8;
    const __nv_bfloat16* gWh0 = Wh + (nrow0 + r0) * KD + sg * 8;
    const __nv_bfloat16* gWh1 = Wh + (nrow0 + r1) * KD + sg * 8;
    const __nv_bfloat16* gWl0 = Wl + (nrow0 + r0) * KD + sg * 8;
    const __nv_bfloat16* gWl1 = Wl + (nrow0 + r1) * KD + sg * 8;

    // --- ldmatrix lane addressing (64B rows) ---
    uint32_t aBase[2], aSwz[2];
#pragma unroll
    for (int mt = 0; mt < 2; mt++) {
        const int r = wm * 32 + mt * 16 + (lane & 15);
        aBase[mt] = (uint32_t)r * 64;
        aSwz[mt]  = (uint32_t)(((r >> 1) & 3) << 4);
    }
    const uint32_t cselA = (uint32_t)(((lane >> 4) & 1) * 16);
    uint32_t bBase[4], bSwz[4];
#pragma unroll
    for (int g = 0; g < 4; g++) {
        const int r = wn * 64 + g * 16 + (lane & 7) + ((lane >> 4) & 1) * 8;
        bBase[g] = (uint32_t)r * 64;
        bSwz[g]  = (uint32_t)(((r >> 1) & 3) << 4);
    }
    const uint32_t cselB = (uint32_t)(((lane >> 3) & 1) * 16);

    float acc[2][8][4];
#pragma unroll
    for (int mt = 0; mt < 2; mt++)
#pragma unroll
        for (int nt = 0; nt < 8; nt++)
#pragma unroll
            for (int r = 0; r < 4; r++) acc[mt][nt][r] = 0.0f;

    auto load_chunk = [&](int ch, int stg) {
        const uint32_t sb = smem_base + (uint32_t)stg * STG_BYTES;
        const int kb = ch * GBK;
        CP_ASYNC16(sb + T_AH + so0, gAh0 + kb);
        CP_ASYNC16(sb + T_AH + so1, gAh1 + kb);
        CP_ASYNC16(sb + T_AL + so0, gAl0 + kb);
        CP_ASYNC16(sb + T_AL + so1, gAl1 + kb);
        CP_ASYNC16(sb + T_WH + so0, gWh0 + kb);
        CP_ASYNC16(sb + T_WH + so1, gWh1 + kb);
        CP_ASYNC16(sb + T_WL + so0, gWl0 + kb);
        CP_ASYNC16(sb + T_WL + so1, gWl1 + kb);
        CP_COMMIT();
    };

    load_chunk(0, 0);
    load_chunk(1, 1);

#pragma unroll 1
    for (int ch = 0; ch < NCHUNK; ch++) {
        if (ch + 1 < NCHUNK) { CP_WAIT(1); } else { CP_WAIT(0); }
        __syncthreads();
        if (ch + 2 < NCHUNK) load_chunk(ch + 2, (ch + 2) % 3);

        const uint32_t sb = smem_base + (uint32_t)(ch % 3) * STG_BYTES;
#pragma unroll
        for (int ks = 0; ks < 2; ks++) {
            const uint32_t kb = (uint32_t)(ks * 32);
            uint32_t ah[2][4], al[2][4];
#pragma unroll
            for (int mt = 0; mt < 2; mt++) {
                const uint32_t off = aBase[mt] + ((kb + cselA) ^ aSwz[mt]);
                LDSM_X4(ah[mt][0], ah[mt][1], ah[mt][2], ah[mt][3], sb + T_AH + off);
                LDSM_X4(al[mt][0], al[mt][1], al[mt][2], al[mt][3], sb + T_AL + off);
            }
#pragma unroll
            for (int gg = 0; gg < 2; gg++) {
                uint32_t bh[2][4], bl[2][4];
#pragma unroll
                for (int gi = 0; gi < 2; gi++) {
                    const int g = gg * 2 + gi;
                    const uint32_t boff = bBase[g] + ((kb + cselB) ^ bSwz[g]);
                    LDSM_X4(bh[gi][0], bh[gi][1], bh[gi][2], bh[gi][3], sb + T_WH + boff);
                    LDSM_X4(bl[gi][0], bl[gi][1], bl[gi][2], bl[gi][3], sb + T_WL + boff);
                }
                // term AhBh — 8 distinct accumulators
#pragma unroll
                for (int mt = 0; mt < 2; mt++)
#pragma unroll
                    for (int gi = 0; gi < 2; gi++) {
                        const int nt = (gg * 2 + gi) * 2;
                        MMA16816(acc[mt][nt],     ah[mt], bh[gi][0], bh[gi][1]);
                        MMA16816(acc[mt][nt + 1], ah[mt], bh[gi][2], bh[gi][3]);
                    }
                // term AhBl
#pragma unroll
                for (int mt = 0; mt < 2; mt++)
#pragma unroll
                    for (int gi = 0; gi < 2; gi++) {
                        const int nt = (gg * 2 + gi) * 2;
                        MMA16816(acc[mt][nt],     ah[mt], bl[gi][0], bl[gi][1]);
                        MMA16816(acc[mt][nt + 1], ah[mt], bl[gi][2], bl[gi][3]);
                    }
                // term AlBh
#pragma unroll
                for (int mt = 0; mt < 2; mt++)
#pragma unroll
                    for (int gi = 0; gi < 2; gi++) {
                        const int nt = (gg * 2 + gi) * 2;
                        MMA16816(acc[mt][nt],     al[mt], bh[gi][0], bh[gi][1]);
                        MMA16816(acc[mt][nt + 1], al[mt], bh[gi][2], bh[gi][3]);
                    }
            }
        }
    }

    // Epilogue (C stride is always E_=1024)
    const int qr = lane >> 2;
    const int qc = (lane & 3) * 2;
#pragma unroll
    for (int mt = 0; mt < 2; mt++) {
        const size_t r0e = mrow0 + wm * 32 + mt * 16 + qr;
        const int bb = (int)(r0e >> 11);
#pragma unroll
        for (int nt = 0; nt < 8; nt++) {
            const size_t col = nrow0 + wn * 64 + nt * 8 + qc;
            float a0 = acc[mt][nt][0], a1 = acc[mt][nt][1];
            float a2 = acc[mt][nt][2], a3 = acc[mt][nt][3];
            if (ADDY) {
                const float y0 = __ldg(yv + (size_t)bb * E_ + col);
                const float y1 = __ldg(yv + (size_t)bb * E_ + col + 1);
                a0 += y0; a1 += y1; a2 += y0; a3 += y1;
            }
            *(float2*)(C + r0e * E_ + col)       = make_float2(a0, a1);
            *(float2*)(C + (r0e + 8) * E_ + col) = make_float2(a2, a3);
        }
    }
}

// ---------------------------------------------------------------------------
// fp32 -> bf16 hi/lo split conversion (full width)
// ---------------------------------------------------------------------------
__global__ __launch_bounds__(256) void conv_split(
    const float* __restrict__ in, __nv_bfloat16* __restrict__ hi,
    __nv_bfloat16* __restrict__ lo, int n4)
{
    int idx = blockIdx.x * 256 + threadIdx.x;
    if (idx >= n4) return;
    float4 v = ((const float4*)in)[idx];
    __nv_bfloat16 h0 = __float2bfloat16(v.x), h1 = __float2bfloat16(v.y);
    __nv_bfloat16 h2 = __float2bfloat16(v.z), h3 = __float2bfloat16(v.w);
    __nv_bfloat16 l0 = __float2bfloat16(v.x - __bfloat162float(h0));
    __nv_bfloat16 l1 = __float2bfloat16(v.y - __bfloat162float(h1));
    __nv_bfloat16 l2 = __float2bfloat16(v.z - __bfloat162float(h2));
    __nv_bfloat16 l3 = __float2bfloat16(v.w - __bfloat162float(h3));
    __nv_bfloat162 hp0; hp0.x = h0; hp0.y = h1;
    __nv_bfloat162 hp1; hp1.x = h2; hp1.y = h3;
    __nv_bfloat162 lp0; lp0.x = l0; lp0.y = l1;
    __nv_bfloat162 lp1; lp1.x = l2; lp1.y = l3;
    uint2 hw, lw;
    hw.x = *(uint32_t*)&hp0; hw.y = *(uint32_t*)&hp1;
    lw.x = *(uint32_t*)&lp0; lw.y = *(uint32_t*)&lp1;
    ((uint2*)hi)[idx] = hw;
    ((uint2*)lo)[idx] = lw;
}

// ---------------------------------------------------------------------------
// W_out packed split: rows 1024, K cols {0:384, 640:1024} -> [1024, 768]
// ---------------------------------------------------------------------------
__global__ __launch_bounds__(256) void conv_split_pack(
    const float* __restrict__ in, __nv_bfloat16* __restrict__ hi,
    __nv_bfloat16* __restrict__ lo)
{
    int idx = blockIdx.x * 256 + threadIdx.x;   // over E_*KP_/4
    if (idx >= E_ * KP_ / 4) return;
    const int pos = idx * 4;
    const int n   = pos / KP_;
    const int kp  = pos % KP_;
    const int k   = kp < 384 ? kp : kp + 256;
    float4 v = *(const float4*)(in + (size_t)n * E_ + k);
    __nv_bfloat16 h0 = __float2bfloat16(v.x), h1 = __float2bfloat16(v.y);
    __nv_bfloat16 h2 = __float2bfloat16(v.z), h3 = __float2bfloat16(v.w);
    __nv_bfloat16 l0 = __float2bfloat16(v.x - __bfloat162float(h0));
    __nv_bfloat16 l1 = __float2bfloat16(v.y - __bfloat162float(h1));
    __nv_bfloat16 l2 = __float2bfloat16(v.z - __bfloat162float(h2));
    __nv_bfloat16 l3 = __float2bfloat16(v.w - __bfloat162float(h3));
    __nv_bfloat162 hp0; hp0.x = h0; hp0.y = h1;
    __nv_bfloat162 hp1; hp1.x = h2; hp1.y = h3;
    __nv_bfloat162 lp0; lp0.x = l0; lp0.y = l1;
    __nv_bfloat162 lp1; lp1.x = l2; lp1.y = l3;
    uint2 hw, lw;
    hw.x = *(uint32_t*)&hp0; hw.y = *(uint32_t*)&hp1;
    lw.x = *(uint32_t*)&lp0; lw.y = *(uint32_t*)&lp1;
    ((uint2*)hi)[idx] = hw;
    ((uint2*)lo)[idx] = lw;
}

__device__ __constant__ float c_wt[RAD + 1] = {
    1.0f, 0.60653066f, 0.13533528f, 0.011108997f, 3.3546263e-4f, 3.7266532e-6f};

// ---------------------------------------------------------------------------
// Gaussian smoothing, 6 non-constant heads only, packed output [M, 768].
// ---------------------------------------------------------------------------
__global__ __launch_bounds__(192) void smooth_pack(
    const float* __restrict__ V, __nv_bfloat16* __restrict__ Uh,
    __nv_bfloat16* __restrict__ Ul)
{
    const int n = blockIdx.x;        // b*L + q
    const int b = n >> 11;
    const int q = n & (L_ - 1);
    const int kp = threadIdx.x * 4;  // packed col
    const int hp = kp >> 7;          // 0..5
    const int vcol = kp < 384 ? kp : kp + 256;

    int c;
    switch (hp % 3) {
        case 0:  c = q;     break;   // center
        case 1:  c = q - 1; break;   // left
        default: c = q + 1; break;   // right
    }

    float ax = 0.f, ay = 0.f, az = 0.f, aw = 0.f, wsum = 0.f;
#pragma unroll
    for (int d = -RAD; d <= RAD; d++) {
        const int j = c + d;
        if (j >= 0 && j < L_) {
            const float w = c_wt[d < 0 ? -d : d];
            wsum += w;
            const float4 v = *(const float4*)(V + ((size_t)b * L_ + j) * E_ + vcol);
            ax = fmaf(w, v.x, ax); ay = fmaf(w, v.y, ay);
            az = fmaf(w, v.z, az); aw = fmaf(w, v.w, aw);
        }
    }
    const float inv = 1.0f / wsum;
    ax *= inv; ay *= inv; az *= inv; aw *= inv;

    __nv_bfloat16 h0 = __float2bfloat16(ax), h1 = __float2bfloat16(ay);
    __nv_bfloat16 h2 = __float2bfloat16(az), h3 = __float2bfloat16(aw);
    __nv_bfloat16 l0 = __float2bfloat16(ax - __bfloat162float(h0));
    __nv_bfloat16 l1 = __float2bfloat16(ay - __bfloat162float(h1));
    __nv_bfloat16 l2 = __float2bfloat16(az - __bfloat162float(h2));
    __nv_bfloat16 l3 = __float2bfloat16(aw - __bfloat162float(h3));
    __nv_bfloat162 hp0; hp0.x = h0; hp0.y = h1;
    __nv_bfloat162 hp1; hp1.x = h2; hp1.y = h3;
    __nv_bfloat162 lp0; lp0.x = l0; lp0.y = l1;
    __nv_bfloat162 lp1; lp1.x = l2; lp1.y = l3;
    uint2 hw, lw;
    hw.x = *(uint32_t*)&hp0; hw.y = *(uint32_t*)&hp1;
    lw.x = *(uint32_t*)&lp0; lw.y = *(uint32_t*)&lp1;
    const size_t o = ((size_t)n * KP_ + kp) >> 2;
    ((uint2*)Uh)[o] = hw;
    ((uint2*)Ul)[o] = lw;
}

// ---------------------------------------------------------------------------
// Per-batch constant-head values: ubar[b][p], p in 0..255 (V col 384+p).
// ---------------------------------------------------------------------------
__global__ void ubar_kernel(const float* __restrict__ V, float* __restrict__ ubar)
{
    const int b = blockIdx.x;
    const int p = threadIdx.x;      // 0..255
    const int c = 384 + p;
    float acc = 0.f, wsum = 0.f;
    if (p < 128) {
#pragma unroll
        for (int j = 0; j <= RAD; j++) {
            const float w = c_wt[j];
            wsum += w;
            acc = fmaf(w, V[((size_t)b * L_ + j) * E_ + c], acc);
        }
    } else {
#pragma unroll
        for (int d = 0; d <= RAD; d++) {
            const float w = c_wt[d];
            wsum += w;
            acc = fmaf(w, V[((size_t)b * L_ + (L_ - 1 - d)) * E_ + c], acc);
        }
    }
    ubar[b * 256 + p] = acc / wsum;
}

// ---------------------------------------------------------------------------
// y[b][n] = sum_p ubar[b][p] * W_out[n][384+p]   (fp32, exact)
// ---------------------------------------------------------------------------
__global__ __launch_bounds__(256) void yvec_kernel(
    const float* __restrict__ ubar, const float* __restrict__ Wout,
    float* __restrict__ yv)
{
    __shared__ float us[256];
    const int b = blockIdx.x >> 2;
    const int n = (blockIdx.x & 3) * 256 + threadIdx.x;
    us[threadIdx.x] = ubar[b * 256 + threadIdx.x];
    __syncthreads();
    float acc = 0.f;
    const float* wr = Wout + (size_t)n * E_ + 384;
#pragma unroll 8
    for (int p = 0; p < 256; p++) acc = fmaf(us[p], wr[p], acc);
    yv[b * E_ + n] = acc;
}

// ---------------------------------------------------------------------------
extern "C" void kernel_launch(void* const* d_in, const int* in_sizes, int n_in,
                              void* d_out, int out_size)
{
    (void)in_sizes; (void)n_in; (void)out_size;
    const float* x     = (const float*)d_in[0];
    const float* W_in  = (const float*)d_in[1];
    const float* W_out = (const float*)d_in[2];
    float* out = (float*)d_out;

    __nv_bfloat16 *Xh, *Xl, *Wih, *Wil, *Wph, *Wpl, *Uh, *Ul;
    float *Vf, *ubar, *yv;
    cudaGetSymbolAddress((void**)&Xh, g_Xh);
    cudaGetSymbolAddress((void**)&Xl, g_Xl);
    cudaGetSymbolAddress((void**)&Wih, g_Wih);
    cudaGetSymbolAddress((void**)&Wil, g_Wil);
    cudaGetSymbolAddress((void**)&Wph, g_Wph);
    cudaGetSymbolAddress((void**)&Wpl, g_Wpl);
    cudaGetSymbolAddress((void**)&Vf, g_Vf);
    cudaGetSymbolAddress((void**)&Uh, g_Uh);
    cudaGetSymbolAddress((void**)&Ul, g_Ul);
    cudaGetSymbolAddress((void**)&ubar, g_ubar);
    cudaGetSymbolAddress((void**)&yv, g_yv);

    cudaFuncSetAttribute(gemm_mma<E_, false>, cudaFuncAttributeMaxDynamicSharedMemorySize, SM_TOTAL);
    cudaFuncSetAttribute(gemm_mma<KP_, true>, cudaFuncAttributeMaxDynamicSharedMemorySize, SM_TOTAL);

    // Split conversions
    conv_split<<<(M_ * E_ / 4 + 255) / 256, 256>>>(x, Xh, Xl, M_ * E_ / 4);
    conv_split<<<(E_ * E_ / 4 + 255) / 256, 256>>>(W_in, Wih, Wil, E_ * E_ / 4);
    conv_split_pack<<<(E_ * KP_ / 4 + 255) / 256, 256>>>(W_out, Wph, Wpl);

    dim3 gridGemm(E_ / GBN, M_ / GBM);   // (8, 128)
    // V = X @ W_in^T  (fp32, full K)
    gemm_mma<E_, false><<<gridGemm, 256, SM_TOTAL>>>(Xh, Xl, Wih, Wil, Vf, nullptr);
    // per-batch constant-head path
    ubar_kernel<<<B_, 256>>>(Vf, ubar);
    yvec_kernel<<<B_ * 4, 256>>>(ubar, W_out, yv);
    // U (packed, 6 heads) = gaussian smooth of V
    smooth_pack<<<M_, 192>>>(Vf, Uh, Ul);
    // out = U_packed @ W_out_packed^T + broadcast(yv)
    gemm_mma<KP_, true><<<gridGemm, 256, SM_TOTAL>>>(Uh, Ul, Wph, Wpl, out, yv);
}